// round 14
// baseline (speedup 1.0000x reference)
#include <cuda_runtime.h>
#include <cstdint>

// Problem dims (fixed)
#define Bv 64
#define Hv 128
#define Wv 128
#define Cv 3
#define Nv 10

#define ROWS 32                // output rows per CTA
#define SRR (ROWS + 4)         // 36 strip rows
#define PXB 32                 // pixels (width) per CTA (8 per warp)
#define SCV (PXB + 4)          // 36 valid strip cols
#define SST 44                 // strip row stride (44 % 32 = 12, conflict-free)
#define NT 128                 // 4 warps, one 8-px col tile each

__device__ __forceinline__ uint32_t to_tf32(float v) {
    uint32_t u;
    asm("cvt.rna.tf32.f32 %0, %1;" : "=r"(u) : "f"(v));
    return u;
}

__device__ __forceinline__ void mma_tf32(float c[4], const uint32_t a[4],
                                         uint32_t b0, uint32_t b1) {
    asm("mma.sync.aligned.m16n8k8.row.col.f32.tf32.tf32.f32 "
        "{%0,%1,%2,%3}, {%4,%5,%6,%7}, {%8,%9}, {%0,%1,%2,%3};"
        : "+f"(c[0]), "+f"(c[1]), "+f"(c[2]), "+f"(c[3])
        : "r"(a[0]), "r"(a[1]), "r"(a[2]), "r"(a[3]), "r"(b0), "r"(b1));
}

// out[n][b][c][h][w] = sum_{kh,kw} images[b][h+kh-2][w+kw-2][c] * kernels[b][kh][kw][n]
// GEMM per (b,c): M = n (16, pad from 10), N = 8 pixels, K = kw slots (kh-major,
// k = 8*kh + kw; kw 5..7 zero-weighted -> image fragments unmasked).
// A = weights (register-resident), B = image fragment. 8 px/warp -> acc ring is
// 20 regs; __launch_bounds__(128,7) lifts occupancy to 7 CTAs/SM.
__global__ __launch_bounds__(NT, 7)
void cdna_mma_kernel(const float* __restrict__ images,
                     const float* __restrict__ kernels,
                     float* __restrict__ out)
{
    __shared__ float strip[SRR * SST];   // tf32-rounded image strip (finite everywhere)
    __shared__ float Wsm[40][16];        // tf32-rounded weights [k=8kh+kw][n], zero pad

    const int tid  = threadIdx.x;
    const int lane = tid & 31;
    const int wrp  = tid >> 5;         // 0..3: 8-px column tile
    const int g    = lane >> 2;        // 0..7
    const int tg   = lane & 3;         // 0..3

    const int bx = blockIdx.x & 3;     // width quarter
    const int rt = blockIdx.x >> 2;    // row tile 0..3
    const int c  = blockIdx.y;
    const int b  = blockIdx.z;
    const int r0 = rt * ROWS;
    const int px0 = bx * PXB;

    // ---- stage W: [k=40][n=16], kh-major slots, tf32-rounded, pad -> 0 ----
    for (int i = tid; i < 640; i += NT) {
        int k = i >> 4, n = i & 15;
        int s = k >> 3, t = k & 7;
        float v = 0.0f;
        if (t < 5 && n < Nv) v = kernels[(b * 25 + s * 5 + t) * Nv + n];
        Wsm[k][n] = __uint_as_float(to_tf32(v));
    }

    // ---- stage strip: FULL stride staged finite (zero outside image) ----
    const float* imgb = images + ((size_t)b * Hv) * (Wv * Cv) + c;
    #pragma unroll
    for (int it = 0; it < (SRR * SST + NT - 1) / NT; it++) {
        int i = it * NT + tid;
        if (i < SRR * SST) {
            int r  = i / SST;
            int cc = i - r * SST;
            int gh = r0 + r - 2;
            int gw = px0 + cc - 2;
            float v = 0.0f;
            if (gh >= 0 && gh < Hv && gw >= 0 && gw < Wv)
                v = imgb[(gh * Wv + gw) * Cv];
            strip[r * SST + cc] = __uint_as_float(to_tf32(v));
        }
    }
    __syncthreads();

    // ---- A (weight) fragments, resident ----
    uint32_t wf[5][4];
    #pragma unroll
    for (int s = 0; s < 5; s++) {
        wf[s][0] = __float_as_uint(Wsm[8 * s + tg][g]);
        wf[s][1] = __float_as_uint(Wsm[8 * s + tg][g + 8]);
        wf[s][2] = __float_as_uint(Wsm[8 * s + tg + 4][g]);
        wf[s][3] = __float_as_uint(Wsm[8 * s + tg + 4][g + 8]);
    }

    const size_t ns = (size_t)Bv * Cv * Hv * Wv;
    float* outbc = out + (((size_t)b * Cv + c) * Hv + r0) * Wv + px0;
    const float* sbase = strip + wrp * 8 + g;

    // ---- 5-row accumulator ring; walk 36 strip rows ----
    float acc[5][4] = {};

    #pragma unroll
    for (int ai = 0; ai < SRR; ai++) {
        const float* sr = sbase + ai * SST;
        // B fragment: B[k=tg][n=g] = px(g+tg), B[k=tg+4][n=g] = px(g+tg+4)
        const uint32_t f0 = __float_as_uint(sr[tg]);
        const uint32_t f1 = __float_as_uint(sr[tg + 4]);

        #pragma unroll
        for (int s = 0; s < 5; s++) {
            const int r = ai - s;
            if (r >= 0 && r < ROWS)
                mma_tf32(acc[r % 5], wf[s], f0, f1);
        }

        const int rd = ai - 4;          // completed output row
        if (rd >= 0) {
            const int sl = rd % 5;
            // thread holds px pair (2tg, 2tg+1) for n=g and n=g+8 -> STG.64
            float* base = outbc + (size_t)rd * Wv + wrp * 8 + 2 * tg;
            float2 v0 = make_float2(acc[sl][0], acc[sl][1]);
            *reinterpret_cast<float2*>(base + (size_t)g * ns) = v0;
            if (g < 2) {                 // n = 8, 9
                float2 v1 = make_float2(acc[sl][2], acc[sl][3]);
                *reinterpret_cast<float2*>(base + (size_t)(g + 8) * ns) = v1;
            }
            #pragma unroll
            for (int q = 0; q < 4; q++)
                acc[sl][q] = 0.0f;
        }
    }
}

extern "C" void kernel_launch(void* const* d_in, const int* in_sizes, int n_in,
                              void* d_out, int out_size)
{
    const float* images  = (const float*)d_in[0];   // [B,H,W,C]
    const float* kernels = (const float*)d_in[1];   // [B,KH,KW,N]
    float* out = (float*)d_out;                     // [N,B,C,H,W]

    dim3 block(NT, 1, 1);
    dim3 grid((Wv / PXB) * (Hv / ROWS), Cv, Bv);   // (16, 3, 64) = 3072 CTAs
    cdna_mma_kernel<<<grid, block>>>(images, kernels, out);
}